// round 2
// baseline (speedup 1.0000x reference)
#include <cuda_runtime.h>
#include <math.h>

#define B_ 8
#define N_ 1024
#define C_ 768
#define H_ 12
#define DH_ 64
#define NIMG_ 784

// Scratch (static device arrays: allocation-free per harness rules)
__device__ float g_qkv[B_ * N_ * 3 * C_];       // [8192][2304]
__device__ float g_q[B_ * H_ * N_ * DH_];       // [bh][n][d]
__device__ float g_k[B_ * H_ * N_ * DH_];
__device__ float g_v[B_ * H_ * N_ * DH_];
__device__ float g_ao[B_ * N_ * C_];            // attention out, [b*N+n][C]

// ---------------------------------------------------------------------------
// Tiled SGEMM: out[m][n] = dot(A[m][:], W[n][:]) + bias[n]
// A: [M][K] row-major, W: [Nout][K] row-major. BM=BN=64, BK=16, 128 threads,
// 4x8 register tile per thread. M,Nout,K all divisible by tile dims here.
// ---------------------------------------------------------------------------
__global__ void __launch_bounds__(128) sgemm_bias_kernel(
    const float* __restrict__ A, const float* __restrict__ W,
    const float* __restrict__ bias, float* __restrict__ out,
    int M, int Nout, int K)
{
    __shared__ float sA[16][65];  // [k][m] transposed
    __shared__ float sB[16][65];  // [k][n] transposed

    const int t = threadIdx.x;
    const int ty = t >> 3;       // 0..15 -> 4 rows each
    const int tx = t & 7;        // 0..7  -> 8 cols each
    const int m0 = blockIdx.y * 64;
    const int n0 = blockIdx.x * 64;

    float acc[4][8];
#pragma unroll
    for (int i = 0; i < 4; i++)
#pragma unroll
        for (int j = 0; j < 8; j++) acc[i][j] = 0.f;

    for (int k0 = 0; k0 < K; k0 += 16) {
        // Load A tile 64x16 (256 float4, 2 per thread), store transposed
#pragma unroll
        for (int i = 0; i < 2; i++) {
            int idx4 = t + i * 128;          // 0..255
            int row = idx4 >> 2;             // 16/4 = 4 float4 per row
            int c4 = (idx4 & 3) * 4;
            float4 v = *(const float4*)(A + (size_t)(m0 + row) * K + k0 + c4);
            sA[c4 + 0][row] = v.x; sA[c4 + 1][row] = v.y;
            sA[c4 + 2][row] = v.z; sA[c4 + 3][row] = v.w;
        }
#pragma unroll
        for (int i = 0; i < 2; i++) {
            int idx4 = t + i * 128;
            int row = idx4 >> 2;
            int c4 = (idx4 & 3) * 4;
            float4 v = *(const float4*)(W + (size_t)(n0 + row) * K + k0 + c4);
            sB[c4 + 0][row] = v.x; sB[c4 + 1][row] = v.y;
            sB[c4 + 2][row] = v.z; sB[c4 + 3][row] = v.w;
        }
        __syncthreads();

#pragma unroll
        for (int kk = 0; kk < 16; kk++) {
            float a[4], b[8];
#pragma unroll
            for (int i = 0; i < 4; i++) a[i] = sA[kk][ty * 4 + i];
#pragma unroll
            for (int j = 0; j < 8; j++) b[j] = sB[kk][tx * 8 + j];
#pragma unroll
            for (int i = 0; i < 4; i++)
#pragma unroll
                for (int j = 0; j < 8; j++) acc[i][j] = fmaf(a[i], b[j], acc[i][j]);
        }
        __syncthreads();
    }

#pragma unroll
    for (int i = 0; i < 4; i++) {
        size_t ro = (size_t)(m0 + ty * 4 + i) * Nout + n0 + tx * 8;
#pragma unroll
        for (int j = 0; j < 8; j++)
            out[ro + j] = acc[i][j] + bias[n0 + tx * 8 + j];
    }
}

// ---------------------------------------------------------------------------
// RoPE2D + split qkv into q,k,v with [b*H+h][n][d] layout.
// tok dim 64: first 32 = y-half (pos2d[...,0]), last 32 = x-half (pos2d[...,1]).
// Within a 32-half: out[dl]    = t[dl]*cos(a) - t[dl+16]*sin(a)   (dl<16)
//                   out[dl]    = t[dl]*cos(a) + t[dl-16]*sin(a)   (dl>=16)
// with a = pos / 100^(f/16), f = dl & 15. Applied only to n < NIMG.
// ---------------------------------------------------------------------------
__global__ void rope_split_kernel(const int* __restrict__ pos2d)
{
    int idx = blockIdx.x * blockDim.x + threadIdx.x;
    const int total = B_ * N_ * H_ * DH_;
    if (idx >= total) return;

    int d = idx & 63;
    int h = (idx >> 6) % H_;
    int n = (idx / (H_ * DH_)) % N_;
    int b = idx / (N_ * H_ * DH_);

    const float* row = g_qkv + (size_t)(b * N_ + n) * (3 * C_);
    float qv = row[h * 64 + d];
    float kv = row[C_ + h * 64 + d];
    float vv = row[2 * C_ + h * 64 + d];

    if (n < NIMG_) {
        int half = d >> 5;               // 0 = y, 1 = x
        int dl = d & 31;
        int f = dl & 15;
        int pos = pos2d[((size_t)b * NIMG_ + n) * 2 + half];
        float inv = powf(100.0f, -(float)f / 16.0f);
        float ang = (float)pos * inv;
        float s, c;
        sincosf(ang, &s, &c);
        int pd = (dl < 16) ? (d + 16) : (d - 16);
        float sign = (dl < 16) ? -1.0f : 1.0f;
        float qp = row[h * 64 + pd];
        float kp = row[C_ + h * 64 + pd];
        qv = qv * c + sign * qp * s;
        kv = kv * c + sign * kp * s;
    }

    size_t o = ((size_t)(b * H_ + h) * N_ + n) * DH_ + d;
    g_q[o] = qv; g_k[o] = kv; g_v[o] = vv;
}

// ---------------------------------------------------------------------------
// Flash-style fp32 attention. Grid: (N/64 q-tiles, B*H). 128 threads.
// BQ=BK=64, Dh=64. Online softmax, 4x8 register tiles for S and O.
// ---------------------------------------------------------------------------
__global__ void __launch_bounds__(128) attn_kernel(float* __restrict__ out)
{
    __shared__ float sQ[64][65];  // [d][q-row] transposed
    __shared__ float sK[64][65];  // [d][key]   transposed
    __shared__ float sV[64][64];  // [key][d]
    __shared__ float sP[64][65];  // [key][q-row] transposed

    const int t = threadIdx.x;
    const int ty = t >> 3;        // 4 q-rows each
    const int tx = t & 7;         // 8 cols each
    const int bh = blockIdx.y;
    const int q0 = blockIdx.x * 64;

    const float* Q = g_q + ((size_t)bh * N_ + q0) * DH_;
    const float* K = g_k + (size_t)bh * N_ * DH_;
    const float* V = g_v + (size_t)bh * N_ * DH_;

    // Load Q tile transposed (1024 float4, 8 per thread)
#pragma unroll
    for (int i = 0; i < 8; i++) {
        int idx4 = t + i * 128;
        int r = idx4 >> 4;              // 16 float4 per 64-float row
        int c4 = (idx4 & 15) * 4;
        float4 v4 = *(const float4*)(Q + r * 64 + c4);
        sQ[c4 + 0][r] = v4.x; sQ[c4 + 1][r] = v4.y;
        sQ[c4 + 2][r] = v4.z; sQ[c4 + 3][r] = v4.w;
    }

    float m_[4], l_[4], o_[4][8];
#pragma unroll
    for (int i = 0; i < 4; i++) {
        m_[i] = -1e30f; l_[i] = 0.f;
#pragma unroll
        for (int j = 0; j < 8; j++) o_[i][j] = 0.f;
    }

    for (int kb = 0; kb < N_; kb += 64) {
        __syncthreads();  // previous iteration's readers of sK/sV/sP done
#pragma unroll
        for (int i = 0; i < 8; i++) {
            int idx4 = t + i * 128;
            int r = idx4 >> 4;
            int c4 = (idx4 & 15) * 4;
            float4 k4 = *(const float4*)(K + (size_t)(kb + r) * 64 + c4);
            sK[c4 + 0][r] = k4.x; sK[c4 + 1][r] = k4.y;
            sK[c4 + 2][r] = k4.z; sK[c4 + 3][r] = k4.w;
            float4 v4 = *(const float4*)(V + (size_t)(kb + r) * 64 + c4);
            *(float4*)&sV[r][c4] = v4;
        }
        __syncthreads();

        // S = Q * K^T  (rows = queries, cols = keys)
        float s[4][8];
#pragma unroll
        for (int i = 0; i < 4; i++)
#pragma unroll
            for (int j = 0; j < 8; j++) s[i][j] = 0.f;
#pragma unroll
        for (int kk = 0; kk < 64; kk++) {
            float a[4], b[8];
#pragma unroll
            for (int i = 0; i < 4; i++) a[i] = sQ[kk][ty * 4 + i];
#pragma unroll
            for (int j = 0; j < 8; j++) b[j] = sK[kk][tx * 8 + j];
#pragma unroll
            for (int i = 0; i < 4; i++)
#pragma unroll
                for (int j = 0; j < 8; j++) s[i][j] = fmaf(a[i], b[j], s[i][j]);
        }

        const float scale = 0.125f;  // 64^-0.5
#pragma unroll
        for (int i = 0; i < 4; i++) {
            float rm = -1e30f;
#pragma unroll
            for (int j = 0; j < 8; j++) {
                s[i][j] *= scale;
                rm = fmaxf(rm, s[i][j]);
            }
            // reduce across the 8 tx lanes (contiguous lane groups of 8)
#pragma unroll
            for (int off = 1; off < 8; off <<= 1)
                rm = fmaxf(rm, __shfl_xor_sync(0xffffffffu, rm, off));

            float mn = fmaxf(m_[i], rm);
            float corr = __expf(m_[i] - mn);
            m_[i] = mn;
            float rs = 0.f;
#pragma unroll
            for (int j = 0; j < 8; j++) {
                float p = __expf(s[i][j] - mn);
                s[i][j] = p;
                rs += p;
            }
#pragma unroll
            for (int off = 1; off < 8; off <<= 1)
                rs += __shfl_xor_sync(0xffffffffu, rs, off);
            l_[i] = l_[i] * corr + rs;
#pragma unroll
            for (int j = 0; j < 8; j++) o_[i][j] *= corr;
        }

        // stash P transposed: sP[key][q-row]
#pragma unroll
        for (int i = 0; i < 4; i++)
#pragma unroll
            for (int j = 0; j < 8; j++)
                sP[tx * 8 + j][ty * 4 + i] = s[i][j];
        __syncthreads();

        // O += P * V   (rows = queries, cols = head dims)
#pragma unroll
        for (int kk = 0; kk < 64; kk++) {
            float pa[4], vb[8];
#pragma unroll
            for (int i = 0; i < 4; i++) pa[i] = sP[kk][ty * 4 + i];
#pragma unroll
            for (int j = 0; j < 8; j++) vb[j] = sV[kk][tx * 8 + j];
#pragma unroll
            for (int i = 0; i < 4; i++)
#pragma unroll
                for (int j = 0; j < 8; j++) o_[i][j] = fmaf(pa[i], vb[j], o_[i][j]);
        }
    }

    const int b = bh / H_;
    const int h = bh % H_;
#pragma unroll
    for (int i = 0; i < 4; i++) {
        float inv = 1.0f / l_[i];
        size_t ro = ((size_t)b * N_ + q0 + ty * 4 + i) * C_ + h * 64 + tx * 8;
#pragma unroll
        for (int j = 0; j < 8; j++)
            out[ro + j] = o_[i][j] * inv;
    }
}

// ---------------------------------------------------------------------------
extern "C" void kernel_launch(void* const* d_in, const int* in_sizes, int n_in,
                              void* d_out, int out_size)
{
    const float* x_t    = (const float*)d_in[0];
    const float* qkv_w  = (const float*)d_in[1];
    const float* qkv_b  = (const float*)d_in[2];
    const float* proj_w = (const float*)d_in[3];
    const float* proj_b = (const float*)d_in[4];
    const int*   pos2d  = (const int*)d_in[5];
    float* out = (float*)d_out;

    float *p_qkv, *p_ao;
    cudaGetSymbolAddress((void**)&p_qkv, g_qkv);
    cudaGetSymbolAddress((void**)&p_ao, g_ao);

    // 1) QKV GEMM: [8192,768] x [2304,768]^T -> [8192,2304]
    {
        dim3 grid((3 * C_) / 64, (B_ * N_) / 64);
        sgemm_bias_kernel<<<grid, 128>>>(x_t, qkv_w, qkv_b, p_qkv,
                                         B_ * N_, 3 * C_, C_);
    }
    // 2) RoPE2D + split/transpose
    {
        int total = B_ * N_ * H_ * DH_;
        rope_split_kernel<<<(total + 255) / 256, 256>>>(pos2d);
    }
    // 3) Attention
    {
        dim3 grid(N_ / 64, B_ * H_);
        attn_kernel<<<grid, 128>>>(p_ao);
    }
    // 4) Output projection: [8192,768] x [768,768]^T -> [8192,768]
    {
        dim3 grid(C_ / 64, (B_ * N_) / 64);
        sgemm_bias_kernel<<<grid, 128>>>(p_ao, proj_w, proj_b, out,
                                         B_ * N_, C_, C_);
    }
}